// round 13
// baseline (speedup 1.0000x reference)
#include <cuda_runtime.h>
#include <cuda_fp16.h>
#include <cstdint>

#define BATCH 32
#define TLEN  1024
#define HID   128
#define NT    512
#define NCTA  144
#define ROWS_PER_CTA 228      // ceil(32768/144)
#define LOG2E 1.4426950408889634f

#define TILE_B (128 * 144 * 2)         // 36864 B (LD_H=144 halves, 288 B rows)
#define SM_Q   0
#define SM_K0  TILE_B
#define SM_K1  (2 * TILE_B)
#define SM_Y   (3 * TILE_B)            // 2*128 floats
#define SM_TOT (SM_Y + 1024)           // 2*512 floats
#define SMEM_BYTES (SM_TOT + 4096)
#define LD_H   144

__device__ __half    g_xn[(size_t)BATCH * TLEN * HID];  // fp16, k-permuted per 16-group
__device__ float     g_nl2[BATCH * TLEN];               // -lambda * log2(e)
__device__ unsigned  g_bar;                             // grid ticket barrier

__device__ __forceinline__ float ex2f(float x) {
    float y; asm("ex2.approx.ftz.f32 %0, %1;" : "=f"(y) : "f"(x)); return y;
}
__device__ __forceinline__ void mma_f16(float* c, uint32_t a0, uint32_t a1,
                                        uint32_t a2, uint32_t a3,
                                        uint32_t b0, uint32_t b1) {
    asm volatile(
        "mma.sync.aligned.m16n8k16.row.col.f32.f16.f16.f32 "
        "{%0,%1,%2,%3}, {%4,%5,%6,%7}, {%8,%9}, {%0,%1,%2,%3};"
        : "+f"(c[0]), "+f"(c[1]), "+f"(c[2]), "+f"(c[3])
        : "r"(a0), "r"(a1), "r"(a2), "r"(a3), "r"(b0), "r"(b1));
}
__device__ __forceinline__ void cp16(uint32_t dst, const void* src) {      // via L1
    asm volatile("cp.async.ca.shared.global [%0], [%1], 16;" :: "r"(dst), "l"(src));
}
__device__ __forceinline__ void cg16(uint32_t dst, const void* src) {      // L2 only
    asm volatile("cp.async.cg.shared.global [%0], [%1], 16;" :: "r"(dst), "l"(src));
}
__device__ __forceinline__ void cp_wait_all() {
    asm volatile("cp.async.wait_all;" ::: "memory");
}

// ---- one 128x128 key block: GEMM + fragment scan (single sync inside) ----
template<bool DIAG>
__device__ __forceinline__ void process_block(
    const __half* q_h, const __half* b_h, const float* yblk, float* totbuf,
    const float* nl2r, const int* rown, float* carry, float* Sacc, float* Yacc,
    int mrow0, int cb, int cw, int g, int tg)
{
    const unsigned FULL = 0xffffffffu;
    const bool live = !DIAG || (cb <= mrow0);   // fully-masked diag fragments skipped

    float acc[2][4][4];
    #pragma unroll
    for (int mt = 0; mt < 2; mt++)
        #pragma unroll
        for (int nt = 0; nt < 4; nt++)
            #pragma unroll
            for (int j = 0; j < 4; j++) acc[mt][nt][j] = 0.f;

    if (live) {
        #pragma unroll
        for (int ks = 0; ks < 8; ++ks) {
            const int boff = ks * 16 + 4 * tg;
            uint2 a[2][2];
            #pragma unroll
            for (int mt = 0; mt < 2; ++mt) {
                const int r = mrow0 + mt * 16 + g;
                a[mt][0] = *(const uint2*)&q_h[r * LD_H + boff];
                a[mt][1] = *(const uint2*)&q_h[(r + 8) * LD_H + boff];
            }
            #pragma unroll
            for (int nt = 0; nt < 4; ++nt) {
                const int n = cb + nt * 8 + g;
                uint2 b = *(const uint2*)&b_h[n * LD_H + boff];
                mma_f16(acc[0][nt], a[0][0].x, a[0][1].x, a[0][0].y, a[0][1].y, b.x, b.y);
                mma_f16(acc[1][nt], a[1][0].x, a[1][1].x, a[1][0].y, a[1][1].y, b.x, b.y);
            }
        }
    }

    // mask + (x+1)/2
    const int col0 = cb + 2 * tg;
    #pragma unroll
    for (int i = 0; i < 4; ++i) {
        const int mt = i >> 1, c0i = (i & 1) * 2;
        #pragma unroll
        for (int nt = 0; nt < 4; nt++) {
            float va = fmaf(acc[mt][nt][c0i],     0.5f, 0.5f);
            float vb = fmaf(acc[mt][nt][c0i + 1], 0.5f, 0.5f);
            if (DIAG) {
                va = (col0 + nt * 8     < rown[i]) ? va : 0.f;
                vb = (col0 + nt * 8 + 1 < rown[i]) ? vb : 0.f;
            }
            acc[mt][nt][c0i]     = va;
            acc[mt][nt][c0i + 1] = vb;
        }
    }

    // per (row,frag): suffix over the 4 lanes of the group
    float sarr[4][4], ft[4][4];
    #pragma unroll
    for (int i = 0; i < 4; ++i) {
        const int mt = i >> 1, c0i = (i & 1) * 2;
        #pragma unroll
        for (int nt = 0; nt < 4; nt++) {
            float s = acc[mt][nt][c0i] + acc[mt][nt][c0i + 1];
            float u = __shfl_down_sync(FULL, s, 1);
            s += (tg < 3) ? u : 0.f;
            u = __shfl_down_sync(FULL, s, 2);
            s += (tg < 2) ? u : 0.f;
            sarr[i][nt] = s;
            ft[i][nt] = __shfl_sync(FULL, s, (threadIdx.x & 31) & ~3);
        }
    }

    if (tg == 0) {
        #pragma unroll
        for (int i = 0; i < 4; ++i)
            totbuf[cw * 128 + rown[i]] = ft[i][0] + ft[i][1] + ft[i][2] + ft[i][3];
    }
    cp_wait_all();
    __syncthreads();        // totals + prefetched K/y visible, ONE barrier

    float2 yp[4];
    #pragma unroll
    for (int nt = 0; nt < 4; nt++)
        yp[nt] = *(const float2*)&yblk[cb + nt * 8 + 2 * tg];

    #pragma unroll
    for (int i = 0; i < 4; ++i) {
        const int r = rown[i];
        const float c0t = totbuf[r],       c1t = totbuf[128 + r],
                    c2t = totbuf[256 + r], c3t = totbuf[384 + r];
        float base = carry[i];
        if (cw == 0)      base += c1t + c2t + c3t;
        else if (cw == 1) base += c2t + c3t;
        else if (cw == 2) base += c3t;
        carry[i] += c0t + c1t + c2t + c3t;

        if (live) {
            const int mt = i >> 1, c0i = (i & 1) * 2;
            float fsuf = 0.f;
            #pragma unroll
            for (int nt = 3; nt >= 0; --nt) {
                const float va = acc[mt][nt][c0i];
                const float vb = acc[mt][nt][c0i + 1];
                const float sa = base + fsuf + sarr[i][nt];
                const float wa = va * ex2f(nl2r[i] * sa);
                const float wb = vb * ex2f(nl2r[i] * (sa - va));
                Sacc[i] += wa + wb;
                Yacc[i] += yp[nt].x * wa + yp[nt].y * wb;
                fsuf += ft[i][nt];
            }
        }
    }
}

// ---- fused kernel: prep phase -> grid barrier -> main phase ----
__global__ __launch_bounds__(NT, 1)
void ema_kernel(const float* __restrict__ y,
                const int*   __restrict__ seq,
                const float* __restrict__ embd,
                const float* __restrict__ lam_w,
                const float* __restrict__ lam_b,
                float*       __restrict__ out)
{
    extern __shared__ char smem[];
    __half* q_h  = (__half*)(smem + SM_Q);
    __half* k_h0 = (__half*)(smem + SM_K0);
    __half* k_h1 = (__half*)(smem + SM_K1);
    float*  y2   = (float*)(smem + SM_Y);
    float*  tot  = (float*)(smem + SM_TOT);

    const uint32_t q_sa = (uint32_t)__cvta_generic_to_shared(q_h);
    const uint32_t k_sa[2] = { (uint32_t)__cvta_generic_to_shared(k_h0),
                               (uint32_t)__cvta_generic_to_shared(k_h1) };
    const uint32_t y_sa = (uint32_t)__cvta_generic_to_shared(y2);

    const int tid  = threadIdx.x;
    const int lane = tid & 31;
    const int wid  = tid >> 5;
    const unsigned FULL = 0xffffffffu;
    const int bid  = blockIdx.x;

    // ================= Phase 1: prep (each CTA owns a token slice) =========
    {
        const int r0  = bid * ROWS_PER_CTA;
        const int rend = min(r0 + ROWS_PER_CTA, BATCH * TLEN);
        const float lb = lam_b[0];
        for (int row = r0 + wid; row < rend; row += 16) {
            const int e = seq[row];
            const float* w = embd + (size_t)e * HID;
            float v[4] = { w[lane], w[lane+32], w[lane+64], w[lane+96] };
            float ss = v[0]*v[0] + v[1]*v[1] + v[2]*v[2] + v[3]*v[3];
            float dl = v[0]*lam_w[lane] + v[1]*lam_w[lane+32]
                     + v[2]*lam_w[lane+64] + v[3]*lam_w[lane+96];
            #pragma unroll
            for (int off = 16; off; off >>= 1) {
                ss += __shfl_xor_sync(FULL, ss, off);
                dl += __shfl_xor_sync(FULL, dl, off);
            }
            const float inv = rsqrtf(ss);
            __half* dst = g_xn + (size_t)row * HID;
            #pragma unroll
            for (int q = 0; q < 4; ++q) {
                const int c = lane + 32 * q;
                const int gk = c >> 4, u = (c >> 1) & 7, par = c & 1;
                const int slot = (u < 4) ? 2 * u : 2 * (u - 4) + 1;
                dst[gk * 16 + slot * 2 + par] = __float2half_rn(v[q] * inv);
            }
            if (lane == 0) g_nl2[row] = -__expf(dl + lb) * LOG2E;
        }
    }

    // ================= grid ticket barrier (replay-safe, monotonic) ========
    __threadfence();
    __syncthreads();
    if (tid == 0) {
        unsigned ticket = atomicAdd(&g_bar, 1u);
        unsigned target = (ticket / NCTA + 1u) * NCTA;
        while (atomicAdd(&g_bar, 0u) < target) __nanosleep(64);
    }
    __syncthreads();
    __threadfence();

    // ================= Phase 2: main ========================================
    const int g  = lane >> 2;
    const int tg = lane & 3;
    const int mrow0 = (wid >> 2) * 32;
    const int cw    = wid & 3;
    const int cb    = cw * 32;

    // job table: every CTA gets exactly 8 work units
    int jb[2], jq[2], njobs;
    if (bid < 32)       { jb[0] = bid;            jq[0] = 7; njobs = 1; }
    else if (bid < 64)  { jb[0] = bid - 32;  jq[0] = 6; jb[1] = jb[0]; jq[1] = 0; njobs = 2; }
    else if (bid < 96)  { jb[0] = bid - 64;  jq[0] = 5; jb[1] = jb[0]; jq[1] = 1; njobs = 2; }
    else if (bid < 128) { jb[0] = bid - 96;  jq[0] = 4; jb[1] = jb[0]; jq[1] = 2; njobs = 2; }
    else { jb[0] = 2 * (bid - 128); jq[0] = 3; jb[1] = jb[0] + 1; jq[1] = 3; njobs = 2; }

    int rown[4];
    #pragma unroll
    for (int i = 0; i < 4; ++i) rown[i] = mrow0 + 8 * i + g;

    for (int j = 0; j < njobs; ++j) {
        const int batch = jb[j];
        const int qi    = jq[j];
        const int t0    = qi * 128;

        const __half* xbase = g_xn + (size_t)batch * TLEN * HID;
        const float*  ybase = y + batch * TLEN;

        __syncthreads();    // previous job done with smem

        // prologue: Q tile + y(qi)
        {
            const __half* qsrc = xbase + (size_t)t0 * HID;
            #pragma unroll
            for (int i = 0; i < 4; ++i) {
                const int c = tid + i * 512;
                const int r = c >> 4, jj = c & 15;
                cg16(q_sa + r * 288 + jj * 16, (const char*)qsrc + r * 256 + jj * 16);
            }
            if (tid < 32) cp16(y_sa + tid * 16, ybase + qi * 128 + tid * 4);
        }
        float nl2r[4];
        #pragma unroll
        for (int i = 0; i < 4; ++i)
            nl2r[i] = g_nl2[batch * TLEN + t0 + rown[i]];
        cp_wait_all();
        __syncthreads();

        float carry[4] = {0.f, 0.f, 0.f, 0.f};
        float Sacc[4]  = {0.f, 0.f, 0.f, 0.f};
        float Yacc[4]  = {0.f, 0.f, 0.f, 0.f};

        for (int it = 0; it <= qi; ++it) {
            const int kb = qi - it;

            if (kb > 0) {
                const __half* ksrc = xbase + (size_t)(kb - 1) * 128 * HID;
                const uint32_t dst = k_sa[it & 1];
                #pragma unroll
                for (int i = 0; i < 4; ++i) {
                    const int c = tid + i * 512;
                    const int r = c >> 4, jj = c & 15;
                    cg16(dst + r * 288 + jj * 16, (const char*)ksrc + r * 256 + jj * 16);
                }
                if (tid < 32)
                    cp16(y_sa + ((it + 1) & 1) * 512 + tid * 16,
                         ybase + (kb - 1) * 128 + tid * 4);
            }

            float* totbuf = tot + (it & 1) * 512;
            const float* yblk = y2 + (it & 1) * 128;
            if (it == 0) {
                process_block<true>(q_h, q_h, yblk, totbuf, nl2r, rown,
                                    carry, Sacc, Yacc, mrow0, cb, cw, g, tg);
            } else {
                const __half* bsrc = (it & 1) ? k_h0 : k_h1;
                process_block<false>(q_h, bsrc, yblk, totbuf, nl2r, rown,
                                     carry, Sacc, Yacc, mrow0, cb, cw, g, tg);
            }
        }

        // ---- epilogue ----
        __syncthreads();
        #pragma unroll
        for (int i = 0; i < 4; ++i) {
            float s = Sacc[i], yv = Yacc[i];
            s  += __shfl_xor_sync(FULL, s, 1);  s  += __shfl_xor_sync(FULL, s, 2);
            yv += __shfl_xor_sync(FULL, yv, 1); yv += __shfl_xor_sync(FULL, yv, 2);
            if (tg == 0) {
                tot[cw * 128 + rown[i]]       = s;
                tot[512 + cw * 128 + rown[i]] = yv;
            }
        }
        __syncthreads();
        if (cw == 0) {
            #pragma unroll
            for (int i = 0; i < 4; ++i) {
                const int r = rown[i];
                float S = tot[r] + tot[128 + r] + tot[256 + r] + tot[384 + r];
                float Y = tot[512 + r] + tot[640 + r] + tot[768 + r] + tot[896 + r];
                float o = Y / (S + 1e-6f);
                o = fminf(fmaxf(o, 0.01f), 0.99f);
                out[batch * TLEN + t0 + r] = o;
            }
        }
    }
}

extern "C" void kernel_launch(void* const* d_in, const int* in_sizes, int n_in,
                              void* d_out, int out_size)
{
    const float* y    = (const float*)d_in[0];
    const int*   seq  = (const int*)  d_in[1];
    const float* embd = (const float*)d_in[2];
    const float* lw   = (const float*)d_in[3];
    const float* lb   = (const float*)d_in[4];
    float* out = (float*)d_out;

    cudaFuncSetAttribute(ema_kernel,
                         cudaFuncAttributeMaxDynamicSharedMemorySize, SMEM_BYTES);

    ema_kernel<<<NCTA, NT, SMEM_BYTES>>>(y, seq, embd, lw, lb, out);
}

// round 14
// speedup vs baseline: 1.1464x; 1.1464x over previous
#include <cuda_runtime.h>
#include <cuda_fp16.h>
#include <cstdint>

#define BATCH 32
#define TLEN  1024
#define HID   128
#define LD_H  144              // halves per padded row (288 B) — gmem AND smem
#define NT    512
#define LOG2E 1.4426950408889634f

#define TILE_B (128 * LD_H * 2)        // 36864 B
#define SM_Q   0
#define SM_K0  TILE_B
#define SM_K1  (2 * TILE_B)
#define SM_Y   (3 * TILE_B)            // 2*128 floats
#define SM_TOT (SM_Y + 1024)           // 2*512 floats
#define SMEM_BYTES (SM_TOT + 4096)

__device__ __half g_xn[(size_t)BATCH * TLEN * LD_H];  // fp16, kp-interleaved frags
__device__ float  g_nl2[BATCH * TLEN];                // -lambda * log2(e)

__device__ __forceinline__ float ex2f(float x) {
    float y; asm("ex2.approx.ftz.f32 %0, %1;" : "=f"(y) : "f"(x)); return y;
}
__device__ __forceinline__ void mma_f16(float* c, uint32_t a0, uint32_t a1,
                                        uint32_t a2, uint32_t a3,
                                        uint32_t b0, uint32_t b1) {
    asm volatile(
        "mma.sync.aligned.m16n8k16.row.col.f32.f16.f16.f32 "
        "{%0,%1,%2,%3}, {%4,%5,%6,%7}, {%8,%9}, {%0,%1,%2,%3};"
        : "+f"(c[0]), "+f"(c[1]), "+f"(c[2]), "+f"(c[3])
        : "r"(a0), "r"(a1), "r"(a2), "r"(a3), "r"(b0), "r"(b1));
}
__device__ __forceinline__ void cp16(uint32_t dst, const void* src) {      // via L1
    asm volatile("cp.async.ca.shared.global [%0], [%1], 16;" :: "r"(dst), "l"(src));
}
__device__ __forceinline__ void cg16(uint32_t dst, const void* src) {      // L2 only
    asm volatile("cp.async.cg.shared.global [%0], [%1], 16;" :: "r"(dst), "l"(src));
}
__device__ __forceinline__ void cp_wait_all() {
    asm volatile("cp.async.wait_all;" ::: "memory");
}

// ---- Pass 1: normalize each token once; store kp-interleaved fp16 ----
// Row layout (halves): tg-block base {0,32,72,104}; within block: ks*4 + (u>=4)*2 + par
__global__ __launch_bounds__(256)
void prep_kernel(const int* __restrict__ seq,
                 const float* __restrict__ embd,
                 const float* __restrict__ lam_w,
                 const float* __restrict__ lam_b)
{
    const int lane = threadIdx.x & 31;
    const int wid  = threadIdx.x >> 5;
    const int row  = blockIdx.x * 8 + wid;
    const unsigned FULL = 0xffffffffu;

    const int e = seq[row];
    const float* w = embd + (size_t)e * HID;
    float v[4] = { w[lane], w[lane+32], w[lane+64], w[lane+96] };
    float ss = v[0]*v[0] + v[1]*v[1] + v[2]*v[2] + v[3]*v[3];
    float dl = v[0]*lam_w[lane] + v[1]*lam_w[lane+32]
             + v[2]*lam_w[lane+64] + v[3]*lam_w[lane+96];
    #pragma unroll
    for (int off = 16; off; off >>= 1) {
        ss += __shfl_xor_sync(FULL, ss, off);
        dl += __shfl_xor_sync(FULL, dl, off);
    }
    const float inv = rsqrtf(ss);

    __half* dst = g_xn + (size_t)row * LD_H;
    const int u      = (lane >> 1) & 7;            // half2-unit within 16-group
    const int tg     = u & 3;
    const int hi2    = (u >> 2) * 2;               // 0 or 2
    const int tgbase = tg * 32 + (tg >> 1) * 8;    // {0,32,72,104}

    #pragma unroll
    for (int q = 0; q < 4; ++q) {
        const __half h = __float2half_rn(v[q] * inv);
        uint32_t mine = (uint32_t)__half_as_ushort(h);
        uint32_t part = __shfl_down_sync(FULL, mine, 1);
        if (!(lane & 1)) {                          // even lane stores the pair
            const int ks  = (lane >> 4) + 2 * q;    // 0..7
            const int pos = tgbase + ks * 4 + hi2;  // even half index
            *(uint32_t*)(dst + pos) = (part << 16) | mine;
        }
    }
    if (lane == 0) g_nl2[row] = -__expf(dl + lam_b[0]) * LOG2E;
}

// ---- one 128x128 key block: GEMM + fragment scan (single sync inside) ----
template<bool DIAG>
__device__ __forceinline__ void process_block(
    const __half* q_h, const __half* b_h, const float* yblk, float* totbuf,
    const float* nl2r, const int* rown, float* carry, float* Sacc, float* Yacc,
    int mrow0, int cb, int cw, int g, int tg, int tgbase)
{
    const unsigned FULL = 0xffffffffu;
    const bool live = !DIAG || (cb <= mrow0);   // fully-masked diag fragments skipped

    float acc[2][4][4];
    #pragma unroll
    for (int mt = 0; mt < 2; mt++)
        #pragma unroll
        for (int nt = 0; nt < 4; nt++)
            #pragma unroll
            for (int j = 0; j < 4; j++) acc[mt][nt][j] = 0.f;

    if (live) {
        #pragma unroll
        for (int kp = 0; kp < 4; ++kp) {        // two k-steps per iteration
            const int aoff = tgbase + kp * 8;   // halves
            uint4 a0 = *(const uint4*)&q_h[(mrow0 +      g) * LD_H + aoff];
            uint4 a1 = *(const uint4*)&q_h[(mrow0 +  8 + g) * LD_H + aoff];
            uint4 a2 = *(const uint4*)&q_h[(mrow0 + 16 + g) * LD_H + aoff];
            uint4 a3 = *(const uint4*)&q_h[(mrow0 + 24 + g) * LD_H + aoff];
            #pragma unroll
            for (int nt = 0; nt < 4; ++nt) {
                uint4 b = *(const uint4*)&b_h[(cb + nt * 8 + g) * LD_H + aoff];
                mma_f16(acc[0][nt], a0.x, a1.x, a0.y, a1.y, b.x, b.y);   // ks = 2kp
                mma_f16(acc[1][nt], a2.x, a3.x, a2.y, a3.y, b.x, b.y);
                mma_f16(acc[0][nt], a0.z, a1.z, a0.w, a1.w, b.z, b.w);   // ks = 2kp+1
                mma_f16(acc[1][nt], a2.z, a3.z, a2.w, a3.w, b.z, b.w);
            }
        }
    }

    // mask + (x+1)/2
    const int col0 = cb + 2 * tg;
    #pragma unroll
    for (int i = 0; i < 4; ++i) {
        const int mt = i >> 1, c0i = (i & 1) * 2;
        #pragma unroll
        for (int nt = 0; nt < 4; nt++) {
            float va = fmaf(acc[mt][nt][c0i],     0.5f, 0.5f);
            float vb = fmaf(acc[mt][nt][c0i + 1], 0.5f, 0.5f);
            if (DIAG) {
                va = (col0 + nt * 8     < rown[i]) ? va : 0.f;
                vb = (col0 + nt * 8 + 1 < rown[i]) ? vb : 0.f;
            }
            acc[mt][nt][c0i]     = va;
            acc[mt][nt][c0i + 1] = vb;
        }
    }

    // per (row,frag): suffix over the 4 lanes of the group
    float sarr[4][4], ft[4][4];
    #pragma unroll
    for (int i = 0; i < 4; ++i) {
        const int mt = i >> 1, c0i = (i & 1) * 2;
        #pragma unroll
        for (int nt = 0; nt < 4; nt++) {
            float s = acc[mt][nt][c0i] + acc[mt][nt][c0i + 1];
            float u = __shfl_down_sync(FULL, s, 1);
            s += (tg < 3) ? u : 0.f;
            u = __shfl_down_sync(FULL, s, 2);
            s += (tg < 2) ? u : 0.f;
            sarr[i][nt] = s;
            ft[i][nt] = __shfl_sync(FULL, s, (threadIdx.x & 31) & ~3);
        }
    }

    if (tg == 0) {
        #pragma unroll
        for (int i = 0; i < 4; ++i)
            totbuf[cw * 128 + rown[i]] = ft[i][0] + ft[i][1] + ft[i][2] + ft[i][3];
    }
    cp_wait_all();
    __syncthreads();        // totals + prefetched K/y visible, ONE barrier

    float2 yp[4];
    #pragma unroll
    for (int nt = 0; nt < 4; nt++)
        yp[nt] = *(const float2*)&yblk[cb + nt * 8 + 2 * tg];

    #pragma unroll
    for (int i = 0; i < 4; ++i) {
        const int r = rown[i];
        const float c0t = totbuf[r],       c1t = totbuf[128 + r],
                    c2t = totbuf[256 + r], c3t = totbuf[384 + r];
        float base = carry[i];
        if (cw == 0)      base += c1t + c2t + c3t;
        else if (cw == 1) base += c2t + c3t;
        else if (cw == 2) base += c3t;
        carry[i] += c0t + c1t + c2t + c3t;

        if (live) {
            const int mt = i >> 1, c0i = (i & 1) * 2;
            float fsuf = 0.f;
            #pragma unroll
            for (int nt = 3; nt >= 0; --nt) {
                const float va = acc[mt][nt][c0i];
                const float vb = acc[mt][nt][c0i + 1];
                const float sa = base + fsuf + sarr[i][nt];
                const float wa = va * ex2f(nl2r[i] * sa);
                const float wb = vb * ex2f(nl2r[i] * (sa - va));
                Sacc[i] += wa + wb;
                Yacc[i] += yp[nt].x * wa + yp[nt].y * wb;
                fsuf += ft[i][nt];
            }
        }
    }
}

// ---- Pass 2: main kernel, exact 8-unit bins, single wave of 144 CTAs ----
__global__ __launch_bounds__(NT, 1)
void ema_kernel(const float* __restrict__ y, float* __restrict__ out)
{
    extern __shared__ char smem[];
    __half* q_h  = (__half*)(smem + SM_Q);
    __half* k_h0 = (__half*)(smem + SM_K0);
    __half* k_h1 = (__half*)(smem + SM_K1);
    float*  y2   = (float*)(smem + SM_Y);
    float*  tot  = (float*)(smem + SM_TOT);

    const uint32_t q_sa = (uint32_t)__cvta_generic_to_shared(q_h);
    const uint32_t k_sa[2] = { (uint32_t)__cvta_generic_to_shared(k_h0),
                               (uint32_t)__cvta_generic_to_shared(k_h1) };
    const uint32_t y_sa = (uint32_t)__cvta_generic_to_shared(y2);

    const int tid  = threadIdx.x;
    const int lane = tid & 31;
    const int wid  = tid >> 5;
    const unsigned FULL = 0xffffffffu;

    const int g  = lane >> 2;
    const int tg = lane & 3;
    const int tgbase = tg * 32 + (tg >> 1) * 8;
    const int mrow0 = (wid >> 2) * 32;
    const int cw    = wid & 3;
    const int cb    = cw * 32;

    // job table: every CTA gets exactly 8 work units
    const int bid = blockIdx.x;
    int jb[2], jq[2], njobs;
    if (bid < 32)       { jb[0] = bid;            jq[0] = 7; njobs = 1; }
    else if (bid < 64)  { jb[0] = bid - 32;  jq[0] = 6; jb[1] = jb[0]; jq[1] = 0; njobs = 2; }
    else if (bid < 96)  { jb[0] = bid - 64;  jq[0] = 5; jb[1] = jb[0]; jq[1] = 1; njobs = 2; }
    else if (bid < 128) { jb[0] = bid - 96;  jq[0] = 4; jb[1] = jb[0]; jq[1] = 2; njobs = 2; }
    else { jb[0] = 2 * (bid - 128); jq[0] = 3; jb[1] = jb[0] + 1; jq[1] = 3; njobs = 2; }

    int rown[4];
    #pragma unroll
    for (int i = 0; i < 4; ++i) rown[i] = mrow0 + 8 * i + g;

    for (int j = 0; j < njobs; ++j) {
        const int batch = jb[j];
        const int qi    = jq[j];
        const int t0    = qi * 128;

        const __half* xbase = g_xn + (size_t)batch * TLEN * LD_H;
        const float*  ybase = y + batch * TLEN;

        __syncthreads();    // previous job fully done with smem

        // prologue: Q tile (linear 2304 chunks) + y(qi)
        {
            const char* qsrc = (const char*)(xbase + (size_t)t0 * LD_H);
            #pragma unroll
            for (int i = 0; i < 4; ++i) {
                const int c = tid + i * 512;
                cg16(q_sa + c * 16, qsrc + c * 16);
            }
            if (tid < 256) {
                const int c = tid + 2048;
                cg16(q_sa + c * 16, qsrc + c * 16);
            }
            if (tid < 32) cp16(y_sa + tid * 16, ybase + qi * 128 + tid * 4);
        }
        float nl2r[4];
        #pragma unroll
        for (int i = 0; i < 4; ++i)
            nl2r[i] = g_nl2[batch * TLEN + t0 + rown[i]];
        cp_wait_all();
        __syncthreads();

        float carry[4] = {0.f, 0.f, 0.f, 0.f};
        float Sacc[4]  = {0.f, 0.f, 0.f, 0.f};
        float Yacc[4]  = {0.f, 0.f, 0.f, 0.f};

        for (int it = 0; it <= qi; ++it) {
            const int kb = qi - it;

            // prefetch K(kb-1) -> kbuf[it&1], y(kb-1) -> ybuf[(it+1)&1]
            if (kb > 0) {
                const char* ksrc = (const char*)(xbase + (size_t)(kb - 1) * 128 * LD_H);
                const uint32_t dst = k_sa[it & 1];
                #pragma unroll
                for (int i = 0; i < 4; ++i) {
                    const int c = tid + i * 512;
                    cg16(dst + c * 16, ksrc + c * 16);
                }
                if (tid < 256) {
                    const int c = tid + 2048;
                    cg16(dst + c * 16, ksrc + c * 16);
                }
                if (tid < 32)
                    cp16(y_sa + ((it + 1) & 1) * 512 + tid * 16,
                         ybase + (kb - 1) * 128 + tid * 4);
            }

            float* totbuf = tot + (it & 1) * 512;
            const float* yblk = y2 + (it & 1) * 128;
            if (it == 0) {
                process_block<true>(q_h, q_h, yblk, totbuf, nl2r, rown,
                                    carry, Sacc, Yacc, mrow0, cb, cw, g, tg, tgbase);
            } else {
                const __half* bsrc = (it & 1) ? k_h0 : k_h1;   // written at it-1
                process_block<false>(q_h, bsrc, yblk, totbuf, nl2r, rown,
                                     carry, Sacc, Yacc, mrow0, cb, cw, g, tg, tgbase);
            }
        }

        // ---- epilogue ----
        __syncthreads();   // weight loops done reading tot
        #pragma unroll
        for (int i = 0; i < 4; ++i) {
            float s = Sacc[i], yv = Yacc[i];
            s  += __shfl_xor_sync(FULL, s, 1);  s  += __shfl_xor_sync(FULL, s, 2);
            yv += __shfl_xor_sync(FULL, yv, 1); yv += __shfl_xor_sync(FULL, yv, 2);
            if (tg == 0) {
                tot[cw * 128 + rown[i]]       = s;
                tot[512 + cw * 128 + rown[i]] = yv;
            }
        }
        __syncthreads();
        if (cw == 0) {
            #pragma unroll
            for (int i = 0; i < 4; ++i) {
                const int r = rown[i];
                float S = tot[r] + tot[128 + r] + tot[256 + r] + tot[384 + r];
                float Y = tot[512 + r] + tot[640 + r] + tot[768 + r] + tot[896 + r];
                float o = Y / (S + 1e-6f);
                o = fminf(fmaxf(o, 0.01f), 0.99f);
                out[batch * TLEN + t0 + r] = o;
            }
        }
    }
}

extern "C" void kernel_launch(void* const* d_in, const int* in_sizes, int n_in,
                              void* d_out, int out_size)
{
    const float* y    = (const float*)d_in[0];
    const int*   seq  = (const int*)  d_in[1];
    const float* embd = (const float*)d_in[2];
    const float* lw   = (const float*)d_in[3];
    const float* lb   = (const float*)d_in[4];
    float* out = (float*)d_out;

    cudaFuncSetAttribute(ema_kernel,
                         cudaFuncAttributeMaxDynamicSharedMemorySize, SMEM_BYTES);

    prep_kernel<<<BATCH * TLEN / 8, 256>>>(seq, embd, lw, lb);
    ema_kernel<<<144, NT, SMEM_BYTES>>>(y, out);
}